// round 16
// baseline (speedup 1.0000x reference)
#include <cuda_runtime.h>
#include <cuda_fp16.h>

#define N_NODES 50000
#define N_EDGES 1600000
#define IN_C    128
#define HEADS   4
#define OUT_C   16
#define HC      64   // HEADS*OUT_C
#define NSPLIT  4    // parity-split fp16 accumulator buffers
#define NODE_STRIDE (NSPLIT * HC)   // 256 halves = 512B per node

// ---------------- scratch (static device globals; no allocs allowed) --------
// NOTE: __device__ globals are zero-initialized at module load. g_aggh and
// g_denom are kept zeroed as an INVARIANT: k_out re-zeroes them after reading,
// so every kernel_launch invocation (correctness run and each graph replay)
// starts from zeroed accumulators without an init kernel.
__device__ __align__(16) __half g_xwh[N_NODES * HC];       // projected, fp16
__device__ __align__(16) float  g_asrc[N_NODES * HEADS];
__device__ __align__(16) float  g_adst[N_NODES * HEADS];
__device__ __align__(16) float  g_denom[N_NODES * HEADS];  // fp32 (exact norm)
// split-interleaved: [node][split][HC]
__device__ __align__(16) __half g_aggh[(size_t)N_NODES * NODE_STRIDE];

// 8-half vectorized reduction (sm_90+)
__device__ __forceinline__ void red_add_v4h2(__half* addr, unsigned r0,
                                             unsigned r1, unsigned r2,
                                             unsigned r3) {
    asm volatile("red.global.add.noftz.v4.f16x2 [%0], {%1, %2, %3, %4};"
                 :: "l"(addr), "r"(r0), "r"(r1), "r"(r2), "r"(r3)
                 : "memory");
}
__device__ __forceinline__ void red_add_v2f(float* addr, float a, float b) {
    asm volatile("red.global.add.v2.f32 [%0], {%1, %2};"
                 :: "l"(addr), "f"(a), "f"(b) : "memory");
}

// ---------------- K1: xw = x @ W -> fp16, fused attention logits ------------
// 256 threads, 64 rows/block, thread = 4 rows x 4 cols (R8/R12 inner loop).
// x is read DIRECTLY from global (16-lane broadcast, L1-resident 32KB tile)
// instead of staged in smem: smem = 32KB static -> ~7 blocks/SM (was 3).
__global__ void k_proj(const float* __restrict__ x, const float* __restrict__ W,
                       const float* __restrict__ att_src,
                       const float* __restrict__ att_dst, int n) {
    __shared__ float sW[IN_C * HC];    // 32KB
    int tid = threadIdx.x;
    int row0 = blockIdx.x * 64;

    for (int i = tid; i < IN_C * HC / 4; i += 256)
        ((float4*)sW)[i] = ((const float4*)W)[i];
    __syncthreads();

    int rg = tid >> 4;
    int c4 = (tid & 15) * 4;
    const float* xrow[4];
#pragma unroll
    for (int i = 0; i < 4; i++) {
        int r = row0 + rg * 4 + i;
        xrow[i] = x + (size_t)(r < n ? r : n - 1) * IN_C;  // clamp reads
    }
    unsigned long long a0[4], a1[4];
#pragma unroll
    for (int i = 0; i < 4; i++) { a0[i] = 0ull; a1[i] = 0ull; }

#pragma unroll 4
    for (int k = 0; k < IN_C; k++) {
        float4 w = *(const float4*)&sW[k * HC + c4];
        unsigned long long w01, w23;
        asm("mov.b64 %0, {%1, %2};" : "=l"(w01) : "f"(w.x), "f"(w.y));
        asm("mov.b64 %0, {%1, %2};" : "=l"(w23) : "f"(w.z), "f"(w.w));
#pragma unroll
        for (int i = 0; i < 4; i++) {
            float xv = __ldg(xrow[i] + k);   // 16-lane broadcast, L1-hit
            unsigned long long xp;
            asm("mov.b64 %0, {%1, %1};" : "=l"(xp) : "f"(xv));
            asm("fma.rn.f32x2 %0, %1, %2, %0;" : "+l"(a0[i]) : "l"(xp), "l"(w01));
            asm("fma.rn.f32x2 %0, %1, %2, %0;" : "+l"(a1[i]) : "l"(xp), "l"(w23));
        }
    }

    float4 as = *(const float4*)(att_src + c4);
    float4 ad = *(const float4*)(att_dst + c4);
    int h = (tid & 15) >> 2;

#pragma unroll
    for (int i = 0; i < 4; i++) {
        int row = row0 + rg * 4 + i;
        float4 o;
        asm("mov.b64 {%0, %1}, %2;" : "=f"(o.x), "=f"(o.y) : "l"(a0[i]));
        asm("mov.b64 {%0, %1}, %2;" : "=f"(o.z), "=f"(o.w) : "l"(a1[i]));
        if (row < n) {
            __half2 p0 = __floats2half2_rn(o.x, o.y);
            __half2 p1 = __floats2half2_rn(o.z, o.w);
            uint2 u;
            u.x = *(unsigned*)&p0;
            u.y = *(unsigned*)&p1;
            *(uint2*)&g_xwh[row * HC + c4] = u;
        }
        float ss = o.x * as.x + o.y * as.y + o.z * as.z + o.w * as.w;
        float sd = o.x * ad.x + o.y * ad.y + o.z * ad.z + o.w * ad.w;
        ss += __shfl_down_sync(0xffffffffu, ss, 2);
        ss += __shfl_down_sync(0xffffffffu, ss, 1);
        sd += __shfl_down_sync(0xffffffffu, sd, 2);
        sd += __shfl_down_sync(0xffffffffu, sd, 1);
        if ((tid & 3) == 0 && row < n) {
            g_asrc[row * 4 + h] = ss;
            g_adst[row * 4 + h] = sd;
        }
    }
}

// ---------------- K2: fused edge pass — 8 threads/edge (R12 verbatim) -------
// Thread q (0..7): head h=q>>1, channels [8q,8q+8) = 1 uint4 gather +
// 1 red.v4h2. Denominator: shfl_xor(ex,2) pairs partner heads; q in {0,4}
// issues ONE red.v2.f32 covering 2 heads -> 2 denom lanes/edge.
__global__ void k_edge(const int* __restrict__ ei, int e) {
    int gid = blockIdx.x * blockDim.x + threadIdx.x;
    int eid = gid >> 3;
    bool valid = eid < e;
    int eidc = valid ? eid : e - 1;
    int q = gid & 7;
    int h = q >> 1;
    int s = __ldg(ei + eidc);
    int d = __ldg(ei + e + eidc);
    float a = g_asrc[s * 4 + h] + g_adst[d * 4 + h];
    a = a > 0.f ? a : 0.2f * a;
    float ex = __expf(a);
    float ex2 = __shfl_xor_sync(0xffffffffu, ex, 2);  // partner head's exp

    __half2 exh = __float2half2_rn(ex);
    uint4 u = *(const uint4*)&g_xwh[s * HC + q * 8];
    __half2 m0 = __hmul2(*(__half2*)&u.x, exh);
    __half2 m1 = __hmul2(*(__half2*)&u.y, exh);
    __half2 m2 = __hmul2(*(__half2*)&u.z, exh);
    __half2 m3 = __hmul2(*(__half2*)&u.w, exh);

    if (valid) {
        int b = eid & (NSPLIT - 1);
        red_add_v4h2(g_aggh + (size_t)d * NODE_STRIDE + b * HC + q * 8,
                     *(unsigned*)&m0, *(unsigned*)&m1,
                     *(unsigned*)&m2, *(unsigned*)&m3);
        if ((q & 3) == 0)   // q==0 -> heads {0,1}; q==4 -> heads {2,3}
            red_add_v2f(g_denom + d * 4 + (q >> 1), ex, ex2);
    }
}

// ---------------- K3: combine + normalize + ELU + out proj + SELF-CLEAN -----
// 8 threads/node (one warp = 4 nodes; all 8 readers of a node share a warp,
// so intra-warp program order makes read-then-zero race-free).
__global__ void k_out(const float* __restrict__ bias,
                      const float* __restrict__ W_out,
                      const float* __restrict__ b_out,
                      float* __restrict__ y, int n) {
    int gid = blockIdx.x * blockDim.x + threadIdx.x;
    int node = gid >> 3;
    int q = gid & 7;
    bool valid = node < n;
    int nc = valid ? node : 0;

    float dn  = g_denom[nc * 4 + (q >> 1)];
    float inv = 1.f / (dn + 1e-16f);

    float acc[8];
#pragma unroll
    for (int i = 0; i < 8; i++) acc[i] = 0.f;
    __half* basep = g_aggh + (size_t)nc * NODE_STRIDE + q * 8;
#pragma unroll
    for (int b = 0; b < NSPLIT; b++) {
        uint4 u = *(const uint4*)(basep + b * HC);
        float2 f0 = __half22float2(*(__half2*)&u.x);
        float2 f1 = __half22float2(*(__half2*)&u.y);
        float2 f2 = __half22float2(*(__half2*)&u.z);
        float2 f3 = __half22float2(*(__half2*)&u.w);
        acc[0] += f0.x; acc[1] += f0.y; acc[2] += f1.x; acc[3] += f1.y;
        acc[4] += f2.x; acc[5] += f2.y; acc[6] += f3.x; acc[7] += f3.y;
    }

    // self-clean for the next invocation (fire-and-forget stores)
    if (valid) {
        uint4 z = make_uint4(0u, 0u, 0u, 0u);
#pragma unroll
        for (int b = 0; b < NSPLIT; b++)
            *(uint4*)(basep + b * HC) = z;
        if (q == 0)
            *(float4*)&g_denom[nc * 4] = make_float4(0.f, 0.f, 0.f, 0.f);
    }

    float4 b0 = *(const float4*)(bias + q * 8);
    float4 b1 = *(const float4*)(bias + q * 8 + 4);
    float4 w0 = *(const float4*)(W_out + q * 8);
    float4 w1 = *(const float4*)(W_out + q * 8 + 4);
    float bb[8] = {b0.x, b0.y, b0.z, b0.w, b1.x, b1.y, b1.z, b1.w};
    float ww[8] = {w0.x, w0.y, w0.z, w0.w, w1.x, w1.y, w1.z, w1.w};

    float p = 0.f;
#pragma unroll
    for (int i = 0; i < 8; i++) {
        float o = acc[i] * inv + bb[i];
        o = o > 0.f ? o : __expf(o) - 1.f;
        p += o * ww[i];
    }
    p += __shfl_down_sync(0xffffffffu, p, 4, 8);
    p += __shfl_down_sync(0xffffffffu, p, 2, 8);
    p += __shfl_down_sync(0xffffffffu, p, 1, 8);
    if (valid && q == 0) y[node] = p + b_out[0];
}

// ---------------- launch -----------------------------------------------------
extern "C" void kernel_launch(void* const* d_in, const int* in_sizes, int n_in,
                              void* d_out, int out_size) {
    const float* x       = (const float*)d_in[0];
    const int*   ei      = (const int*)d_in[1];
    const float* W       = (const float*)d_in[2];
    const float* att_src = (const float*)d_in[3];
    const float* att_dst = (const float*)d_in[4];
    const float* bias    = (const float*)d_in[5];
    const float* W_out   = (const float*)d_in[6];
    const float* b_out   = (const float*)d_in[7];
    float*       y       = (float*)d_out;

    int n = in_sizes[0] / IN_C;   // 50000
    int e = in_sizes[1] / 2;      // 1600000

    const int B = 256;
    k_proj<<<(n + 63) / 64, 256>>>(x, W, att_src, att_dst, n);
    k_edge<<<((size_t)e * 8 + B - 1) / B, B>>>(ei, e);
    k_out<<<(n * 8 + B - 1) / B, B>>>(bias, W_out, b_out, y, n);
}

// round 17
// speedup vs baseline: 1.1847x; 1.1847x over previous
#include <cuda_runtime.h>
#include <cuda_fp16.h>

#define N_NODES 50000
#define N_EDGES 1600000
#define IN_C    128
#define HEADS   4
#define OUT_C   16
#define HC      64   // HEADS*OUT_C
#define NSPLIT  2    // parity-split fp16 accumulator buffers
#define NODE_STRIDE (NSPLIT * HC)   // 128 halves = 256B per node

// ---------------- scratch (static device globals; no allocs allowed) --------
// INVARIANT: g_aggh / g_denom are zero at entry of every kernel_launch call.
// __device__ globals are zero-initialized at load; k_out re-zeroes them after
// reading, so the invariant holds for the correctness run and every replay.
__device__ __align__(16) __half g_xwh[N_NODES * HC];       // projected, fp16
__device__ __align__(16) float  g_asrc[N_NODES * HEADS];
__device__ __align__(16) float  g_adst[N_NODES * HEADS];
__device__ __align__(16) float  g_denom[N_NODES * HEADS];  // fp32 (exact norm)
// split-interleaved: [node][split][HC]
__device__ __align__(16) __half g_aggh[(size_t)N_NODES * NODE_STRIDE];

// 8-half vectorized reduction (sm_90+)
__device__ __forceinline__ void red_add_v4h2(__half* addr, unsigned r0,
                                             unsigned r1, unsigned r2,
                                             unsigned r3) {
    asm volatile("red.global.add.noftz.v4.f16x2 [%0], {%1, %2, %3, %4};"
                 :: "l"(addr), "r"(r0), "r"(r1), "r"(r2), "r"(r3)
                 : "memory");
}
__device__ __forceinline__ void red_add_v2f(float* addr, float a, float b) {
    asm volatile("red.global.add.v2.f32 [%0], {%1, %2};"
                 :: "l"(addr), "f"(a), "f"(b) : "memory");
}

// ---------------- K1: xw = x @ W -> fp16, fused attention logits ------------
// R12 verbatim (best of 5 measured proj variants: 36us).
// 256 threads, 64 rows/block. Thread = 4 rows x 4 cols, packed f32x2 FMA.
__global__ void k_proj(const float* __restrict__ x, const float* __restrict__ W,
                       const float* __restrict__ att_src,
                       const float* __restrict__ att_dst, int n) {
    extern __shared__ float smem[];
    float* sW = smem;
    float* sx = smem + IN_C * HC;
    int tid = threadIdx.x;
    int row0 = blockIdx.x * 64;

    for (int i = tid; i < IN_C * HC / 4; i += 256)
        ((float4*)sW)[i] = ((const float4*)W)[i];
    for (int i = tid; i < 64 * IN_C / 4; i += 256) {
        int r = i >> 5;
        float4 v = make_float4(0.f, 0.f, 0.f, 0.f);
        if (row0 + r < n) v = ((const float4*)x)[(size_t)(row0 + r) * 32 + (i & 31)];
        ((float4*)sx)[i] = v;
    }
    __syncthreads();

    int rg = tid >> 4;
    int c4 = (tid & 15) * 4;
    unsigned long long a0[4], a1[4];
#pragma unroll
    for (int i = 0; i < 4; i++) { a0[i] = 0ull; a1[i] = 0ull; }

#pragma unroll 4
    for (int k = 0; k < IN_C; k++) {
        float4 w = *(const float4*)&sW[k * HC + c4];
        unsigned long long w01, w23;
        asm("mov.b64 %0, {%1, %2};" : "=l"(w01) : "f"(w.x), "f"(w.y));
        asm("mov.b64 %0, {%1, %2};" : "=l"(w23) : "f"(w.z), "f"(w.w));
#pragma unroll
        for (int i = 0; i < 4; i++) {
            float xv = sx[(rg * 4 + i) * IN_C + k];
            unsigned long long xp;
            asm("mov.b64 %0, {%1, %1};" : "=l"(xp) : "f"(xv));
            asm("fma.rn.f32x2 %0, %1, %2, %0;" : "+l"(a0[i]) : "l"(xp), "l"(w01));
            asm("fma.rn.f32x2 %0, %1, %2, %0;" : "+l"(a1[i]) : "l"(xp), "l"(w23));
        }
    }

    float4 as = *(const float4*)(att_src + c4);
    float4 ad = *(const float4*)(att_dst + c4);
    int h = (tid & 15) >> 2;

#pragma unroll
    for (int i = 0; i < 4; i++) {
        int row = row0 + rg * 4 + i;
        float4 o;
        asm("mov.b64 {%0, %1}, %2;" : "=f"(o.x), "=f"(o.y) : "l"(a0[i]));
        asm("mov.b64 {%0, %1}, %2;" : "=f"(o.z), "=f"(o.w) : "l"(a1[i]));
        if (row < n) {
            __half2 p0 = __floats2half2_rn(o.x, o.y);
            __half2 p1 = __floats2half2_rn(o.z, o.w);
            uint2 u;
            u.x = *(unsigned*)&p0;
            u.y = *(unsigned*)&p1;
            *(uint2*)&g_xwh[row * HC + c4] = u;
        }
        float ss = o.x * as.x + o.y * as.y + o.z * as.z + o.w * as.w;
        float sd = o.x * ad.x + o.y * ad.y + o.z * ad.z + o.w * ad.w;
        ss += __shfl_down_sync(0xffffffffu, ss, 2);
        ss += __shfl_down_sync(0xffffffffu, ss, 1);
        sd += __shfl_down_sync(0xffffffffu, sd, 2);
        sd += __shfl_down_sync(0xffffffffu, sd, 1);
        if ((tid & 3) == 0 && row < n) {
            g_asrc[row * 4 + h] = ss;
            g_adst[row * 4 + h] = sd;
        }
    }
}

// ---------------- K2: fused edge pass — 8 threads/edge (R12 verbatim) -------
// Thread q (0..7): head h=q>>1, channels [8q,8q+8) = 1 uint4 gather +
// 1 red.v4h2. Denominator: shfl_xor(ex,2) pairs partner heads; q in {0,4}
// issues ONE red.v2.f32 covering 2 heads -> 2 denom lanes/edge.
__global__ void k_edge(const int* __restrict__ ei, int e) {
    int gid = blockIdx.x * blockDim.x + threadIdx.x;
    int eid = gid >> 3;
    bool valid = eid < e;
    int eidc = valid ? eid : e - 1;
    int q = gid & 7;
    int h = q >> 1;
    int s = __ldg(ei + eidc);
    int d = __ldg(ei + e + eidc);
    float a = g_asrc[s * 4 + h] + g_adst[d * 4 + h];
    a = a > 0.f ? a : 0.2f * a;
    float ex = __expf(a);
    float ex2 = __shfl_xor_sync(0xffffffffu, ex, 2);  // partner head's exp

    __half2 exh = __float2half2_rn(ex);
    uint4 u = *(const uint4*)&g_xwh[s * HC + q * 8];
    __half2 m0 = __hmul2(*(__half2*)&u.x, exh);
    __half2 m1 = __hmul2(*(__half2*)&u.y, exh);
    __half2 m2 = __hmul2(*(__half2*)&u.z, exh);
    __half2 m3 = __hmul2(*(__half2*)&u.w, exh);

    if (valid) {
        int b = eid & (NSPLIT - 1);
        red_add_v4h2(g_aggh + (size_t)d * NODE_STRIDE + b * HC + q * 8,
                     *(unsigned*)&m0, *(unsigned*)&m1,
                     *(unsigned*)&m2, *(unsigned*)&m3);
        if ((q & 3) == 0)   // q==0 -> heads {0,1}; q==4 -> heads {2,3}
            red_add_v2f(g_denom + d * 4 + (q >> 1), ex, ex2);
    }
}

// ---------------- K3: combine + normalize + ELU + out proj + SELF-CLEAN -----
// 8 threads/node; all 8 readers of a node share one warp, so the post-read
// zero-stores are program-ordered after the reads (race-free).
__global__ void k_out(const float* __restrict__ bias,
                      const float* __restrict__ W_out,
                      const float* __restrict__ b_out,
                      float* __restrict__ y, int n) {
    int gid = blockIdx.x * blockDim.x + threadIdx.x;
    int node = gid >> 3;
    int q = gid & 7;
    bool valid = node < n;
    int nc = valid ? node : 0;

    float dn  = g_denom[nc * 4 + (q >> 1)];
    float inv = 1.f / (dn + 1e-16f);

    float acc[8];
#pragma unroll
    for (int i = 0; i < 8; i++) acc[i] = 0.f;
    __half* basep = g_aggh + (size_t)nc * NODE_STRIDE + q * 8;
#pragma unroll
    for (int b = 0; b < NSPLIT; b++) {
        uint4 u = *(const uint4*)(basep + b * HC);
        float2 f0 = __half22float2(*(__half2*)&u.x);
        float2 f1 = __half22float2(*(__half2*)&u.y);
        float2 f2 = __half22float2(*(__half2*)&u.z);
        float2 f3 = __half22float2(*(__half2*)&u.w);
        acc[0] += f0.x; acc[1] += f0.y; acc[2] += f1.x; acc[3] += f1.y;
        acc[4] += f2.x; acc[5] += f2.y; acc[6] += f3.x; acc[7] += f3.y;
    }

    // self-clean for the next invocation (fire-and-forget)
    if (valid) {
        uint4 z = make_uint4(0u, 0u, 0u, 0u);
#pragma unroll
        for (int b = 0; b < NSPLIT; b++)
            *(uint4*)(basep + b * HC) = z;
        if (q == 0)
            *(float4*)&g_denom[nc * 4] = make_float4(0.f, 0.f, 0.f, 0.f);
    }

    float4 b0 = *(const float4*)(bias + q * 8);
    float4 b1 = *(const float4*)(bias + q * 8 + 4);
    float4 w0 = *(const float4*)(W_out + q * 8);
    float4 w1 = *(const float4*)(W_out + q * 8 + 4);
    float bb[8] = {b0.x, b0.y, b0.z, b0.w, b1.x, b1.y, b1.z, b1.w};
    float ww[8] = {w0.x, w0.y, w0.z, w0.w, w1.x, w1.y, w1.z, w1.w};

    float p = 0.f;
#pragma unroll
    for (int i = 0; i < 8; i++) {
        float o = acc[i] * inv + bb[i];
        o = o > 0.f ? o : __expf(o) - 1.f;
        p += o * ww[i];
    }
    p += __shfl_down_sync(0xffffffffu, p, 4, 8);
    p += __shfl_down_sync(0xffffffffu, p, 2, 8);
    p += __shfl_down_sync(0xffffffffu, p, 1, 8);
    if (valid && q == 0) y[node] = p + b_out[0];
}

// ---------------- launch -----------------------------------------------------
extern "C" void kernel_launch(void* const* d_in, const int* in_sizes, int n_in,
                              void* d_out, int out_size) {
    const float* x       = (const float*)d_in[0];
    const int*   ei      = (const int*)d_in[1];
    const float* W       = (const float*)d_in[2];
    const float* att_src = (const float*)d_in[3];
    const float* att_dst = (const float*)d_in[4];
    const float* bias    = (const float*)d_in[5];
    const float* W_out   = (const float*)d_in[6];
    const float* b_out   = (const float*)d_in[7];
    float*       y       = (float*)d_out;

    int n = in_sizes[0] / IN_C;   // 50000
    int e = in_sizes[1] / 2;      // 1600000

    const int B = 256;
    const int proj_smem = (IN_C * HC + 64 * IN_C) * (int)sizeof(float); // 64KB
    cudaFuncSetAttribute(k_proj, cudaFuncAttributeMaxDynamicSharedMemorySize,
                         proj_smem);

    k_proj<<<(n + 63) / 64, 256, proj_smem>>>(x, W, att_src, att_dst, n);
    k_edge<<<((size_t)e * 8 + B - 1) / B, B>>>(ei, e);
    k_out<<<(n * 8 + B - 1) / B, B>>>(bias, W_out, b_out, y, n);
}